// round 11
// baseline (speedup 1.0000x reference)
#include <cuda_runtime.h>
#include <math.h>
#include <stdint.h>

#define BB 8
#define LL 128
#define DD 512
#define EE 64
#define HH 8
#define BL (BB*LL)   // 1024

typedef unsigned long long ull;

__device__ __forceinline__ void fma2(ull &acc, ull a, ull b) {
    asm("fma.rn.f32x2 %0, %1, %2, %0;" : "+l"(acc) : "l"(a), "l"(b));
}
__device__ __forceinline__ void add2(ull &a, ull b) {
    asm("add.rn.f32x2 %0, %0, %1;" : "+l"(a) : "l"(b));
}
__device__ __forceinline__ ull pack2(float x, float y) {
    ull r; asm("mov.b64 %0, {%1,%2};" : "=l"(r) : "f"(x), "f"(y)); return r;
}
__device__ __forceinline__ void unpack2(ull v, float &x, float &y) {
    asm("mov.b64 {%0,%1}, %2;" : "=f"(x), "=f"(y) : "l"(v));
}
__device__ __forceinline__ float fsum2(ull v) {
    float x, y; unpack2(v, x, y); return x + y;
}

// cp.async helpers
__device__ __forceinline__ uint32_t smem_u32(const void* p) {
    uint32_t a;
    asm("{ .reg .u64 t; cvta.to.shared.u64 t, %1; cvt.u32.u64 %0, t; }" : "=r"(a) : "l"(p));
    return a;
}
__device__ __forceinline__ void cp16(uint32_t d, const void* s) {
    asm volatile("cp.async.ca.shared.global [%0], [%1], 16;" :: "r"(d), "l"(s));
}
__device__ __forceinline__ void cp_commit() {
    asm volatile("cp.async.commit_group;" ::: "memory");
}
template<int N> __device__ __forceinline__ void cp_wait() {
    asm volatile("cp.async.wait_group %0;" :: "n"(N) : "memory");
}

// Scratch
__device__ float dQ[BL*DD];
__device__ float dKV[BL*DD];
__device__ float dG[BL*HH*EE];           // [bq][h][e]
__device__ float dS1[BB*HH*LL*LL];       // [bh][q][k]
__device__ float dALPHA[BB*HH*LL*LL];    // [bh][q][k]
__device__ float dWsum[BB*HH*LL*EE];     // [bh][q][e]
__device__ float dATTN[BL*DD];
__device__ float dFFN[BL*DD];

// ---------------------------------------------------------------------------
// 4-stage cp.async f32x2 GEMM, 32m x 64n tile, 128 threads.
// ---------------------------------------------------------------------------
__global__ __launch_bounds__(128) void gemm_ca(
    const float* __restrict__ A,
    const float* __restrict__ B0, float* __restrict__ C0,
    const float* __restrict__ B1, float* __restrict__ C1,
    const float* __restrict__ bias, int K, int N)
{
    __shared__ float As[4][32*36];   // 18.4 KB
    __shared__ float Bs[4][32*64];   // 32 KB

    const float* Bm = blockIdx.z ? B1 : B0;
    float*       Cm = blockIdx.z ? C1 : C0;

    const int t  = threadIdx.x;
    const int tx = t & 15, ty = t >> 4;
    const int m0 = blockIdx.y * 32, n0 = blockIdx.x * 64;

    const uint32_t asb = smem_u32(&As[0][0]);
    const uint32_t bsb = smem_u32(&Bs[0][0]);

    ull acc[4][2] = {};

    #define ISSUE_TILE(buf, k0) do {                                            \
        _Pragma("unroll")                                                       \
        for (int r = 0; r < 2; r++) {                                           \
            int idx = t + r * 128;                                              \
            int m = idx >> 3, k4 = (idx & 7) << 2;                              \
            cp16(asb + (uint32_t)(buf) * 4608u + (uint32_t)(m * 36 + k4) * 4u,  \
                 A + (size_t)(m0 + m) * K + (k0) + k4);                         \
        }                                                                       \
        _Pragma("unroll")                                                       \
        for (int r = 0; r < 4; r++) {                                           \
            int idx = t + r * 128;                                              \
            int kk = idx >> 4, n4 = (idx & 15) << 2;                            \
            cp16(bsb + (uint32_t)(buf) * 8192u + (uint32_t)(kk * 64 + n4) * 4u, \
                 Bm + (size_t)((k0) + kk) * N + n0 + n4);                       \
        }                                                                       \
        cp_commit();                                                            \
    } while (0)

    const int NT = K / 32;
    ISSUE_TILE(0, 0);
    ISSUE_TILE(1, 32);
    ISSUE_TILE(2, 64);

    for (int kt = 0; kt < NT; kt++) {
        if (kt + 2 < NT)      cp_wait<2>();
        else if (kt + 1 < NT) cp_wait<1>();
        else                  cp_wait<0>();
        __syncthreads();
        if (kt + 3 < NT) ISSUE_TILE((kt + 3) & 3, (kt + 3) * 32);

        const int buf = kt & 3;
        #pragma unroll 4
        for (int kk = 0; kk < 32; kk += 2) {
            ull bp00 = *(const ull*)&Bs[buf][kk * 64 + tx * 2];
            ull bp01 = *(const ull*)&Bs[buf][kk * 64 + tx * 2 + 32];
            ull bp10 = *(const ull*)&Bs[buf][(kk + 1) * 64 + tx * 2];
            ull bp11 = *(const ull*)&Bs[buf][(kk + 1) * 64 + tx * 2 + 32];
            #pragma unroll
            for (int i = 0; i < 4; i++) {
                float2 af = *(const float2*)&As[buf][(ty * 4 + i) * 36 + kk];
                ull ad0 = pack2(af.x, af.x);
                ull ad1 = pack2(af.y, af.y);
                fma2(acc[i][0], ad0, bp00);
                fma2(acc[i][1], ad0, bp01);
                fma2(acc[i][0], ad1, bp10);
                fma2(acc[i][1], ad1, bp11);
            }
        }
        __syncthreads();
    }
    #undef ISSUE_TILE

    #pragma unroll
    for (int i = 0; i < 4; i++) {
        int m = m0 + ty * 4 + i;
        float x0, x1, y0, y1;
        unpack2(acc[i][0], x0, x1);
        unpack2(acc[i][1], y0, y1);
        int nA = n0 + tx * 2, nB = nA + 32;
        if (bias) {
            x0 += bias[nA]; x1 += bias[nA + 1];
            y0 += bias[nB]; y1 += bias[nB + 1];
        }
        *(float2*)(Cm + (size_t)m * N + nA) = make_float2(x0, x1);
        *(float2*)(Cm + (size_t)m * N + nB) = make_float2(y0, y1);
    }
}

// ---------------------------------------------------------------------------
// attn 4-stage cp.async GEMM, 32m x 64n tiles: grid (64, 4), K = 192.
// C = [alpha | Wsum] @ [KV_h ; We_h]
// ---------------------------------------------------------------------------
__global__ __launch_bounds__(128) void attn_ca(const float* __restrict__ We)
{
    __shared__ float As[4][32*36];
    __shared__ float Bs[4][32*64];

    const int bh = blockIdx.x, mh = blockIdx.y;
    const int b  = bh >> 3, h = bh & 7;
    const int t  = threadIdx.x;
    const int tx = t & 15, ty = t >> 4;

    const uint32_t asb = smem_u32(&As[0][0]);
    const uint32_t bsb = smem_u32(&Bs[0][0]);

    ull acc[4][2] = {};

    #define ISSUE_ATTN(buf, k0) do {                                            \
        _Pragma("unroll")                                                       \
        for (int r = 0; r < 2; r++) {                                           \
            int idx = t + r * 128;                                              \
            int m = idx >> 3, k4 = (idx & 7) << 2;                              \
            size_t row = (size_t)bh * LL + mh * 32 + m;                         \
            const float* src = ((k0) < 128)                                     \
                ? (dALPHA + row * LL + (k0) + k4)                               \
                : (dWsum  + row * EE + ((k0) - 128) + k4);                      \
            cp16(asb + (uint32_t)(buf) * 4608u + (uint32_t)(m * 36 + k4) * 4u, src); \
        }                                                                       \
        _Pragma("unroll")                                                       \
        for (int r = 0; r < 4; r++) {                                           \
            int idx = t + r * 128;                                              \
            int kk = idx >> 4, n4 = (idx & 15) << 2;                            \
            int kg = (k0) + kk;                                                 \
            const float* src = (kg < 128)                                       \
                ? (dKV + (size_t)(b * LL + kg) * DD + h * 64 + n4)              \
                : (We  + (size_t)(kg - 128) * DD + h * 64 + n4);                \
            cp16(bsb + (uint32_t)(buf) * 8192u + (uint32_t)(kk * 64 + n4) * 4u, src); \
        }                                                                       \
        cp_commit();                                                            \
    } while (0)

    const int NT = 6;   // K = 192
    ISSUE_ATTN(0, 0);
    ISSUE_ATTN(1, 32);
    ISSUE_ATTN(2, 64);

    for (int kt = 0; kt < NT; kt++) {
        if (kt + 2 < NT)      cp_wait<2>();
        else if (kt + 1 < NT) cp_wait<1>();
        else                  cp_wait<0>();
        __syncthreads();
        if (kt + 3 < NT) ISSUE_ATTN((kt + 3) & 3, (kt + 3) * 32);

        const int buf = kt & 3;
        #pragma unroll 4
        for (int kk = 0; kk < 32; kk += 2) {
            ull bp00 = *(const ull*)&Bs[buf][kk * 64 + tx * 2];
            ull bp01 = *(const ull*)&Bs[buf][kk * 64 + tx * 2 + 32];
            ull bp10 = *(const ull*)&Bs[buf][(kk + 1) * 64 + tx * 2];
            ull bp11 = *(const ull*)&Bs[buf][(kk + 1) * 64 + tx * 2 + 32];
            #pragma unroll
            for (int i = 0; i < 4; i++) {
                float2 af = *(const float2*)&As[buf][(ty * 4 + i) * 36 + kk];
                ull ad0 = pack2(af.x, af.x);
                ull ad1 = pack2(af.y, af.y);
                fma2(acc[i][0], ad0, bp00);
                fma2(acc[i][1], ad0, bp01);
                fma2(acc[i][0], ad1, bp10);
                fma2(acc[i][1], ad1, bp11);
            }
        }
        __syncthreads();
    }
    #undef ISSUE_ATTN

    #pragma unroll
    for (int i = 0; i < 4; i++) {
        int m = mh * 32 + ty * 4 + i;
        float* crow = dATTN + ((size_t)(b * LL) + m) * DD + h * 64;
        float x0, x1, y0, y1;
        unpack2(acc[i][0], x0, x1);
        unpack2(acc[i][1], y0, y1);
        *(float2*)(crow + tx * 2)      = make_float2(x0, x1);
        *(float2*)(crow + tx * 2 + 32) = make_float2(y0, y1);
    }
}

// ---------------------------------------------------------------------------
// Merged s1 + g kernel (proven): 256 blocks x 256 threads.
// ---------------------------------------------------------------------------
__global__ __launch_bounds__(256) void s1g_kernel(const float* __restrict__ We)
{
    __shared__ float pool[8320];

    const int bx = blockIdx.x;
    const int t  = threadIdx.x;
    const int tx = t & 15, ty = t >> 4;

    if (bx < 128) {
        float* Qs = pool;            // [64][34]
        float* Ks = pool + 2176;     // [128][34]
        const int bh = bx >> 1, mh = bx & 1;
        const int b  = bh >> 3, h = bh & 7;

        ull acc[4][8] = {};

        for (int c0 = 0; c0 < 64; c0 += 32) {
            #pragma unroll
            for (int r = 0; r < 2; r++) {
                int idx = t + r * 256;
                int m   = idx >> 3;
                int c4  = (idx & 7) << 2;
                float4 v = *(const float4*)(dQ + (size_t)(b * LL + mh * 64 + m) * DD + h * 64 + c0 + c4);
                *(float2*)(Qs + m * 34 + c4)     = make_float2(v.x, v.y);
                *(float2*)(Qs + m * 34 + c4 + 2) = make_float2(v.z, v.w);
            }
            #pragma unroll
            for (int r = 0; r < 4; r++) {
                int idx = t + r * 256;
                int n   = idx >> 3;
                int c4  = (idx & 7) << 2;
                float4 v = *(const float4*)(dKV + (size_t)(b * LL + n) * DD + h * 64 + c0 + c4);
                *(float2*)(Ks + n * 34 + c4)     = make_float2(v.x, v.y);
                *(float2*)(Ks + n * 34 + c4 + 2) = make_float2(v.z, v.w);
            }
            __syncthreads();

            #pragma unroll
            for (int cc = 0; cc < 32; cc += 2) {
                ull a[4], b2[8];
                #pragma unroll
                for (int i = 0; i < 4; i++) a[i]  = *(const ull*)(Qs + (ty * 4 + i) * 34 + cc);
                #pragma unroll
                for (int j = 0; j < 8; j++) b2[j] = *(const ull*)(Ks + (tx + 16 * j) * 34 + cc);
                #pragma unroll
                for (int i = 0; i < 4; i++)
                    #pragma unroll
                    for (int j = 0; j < 8; j++)
                        fma2(acc[i][j], a[i], b2[j]);
            }
            __syncthreads();
        }

        #pragma unroll
        for (int i = 0; i < 4; i++) {
            int m = mh * 64 + ty * 4 + i;
            #pragma unroll
            for (int j = 0; j < 8; j++)
                dS1[((size_t)bh * LL + m) * LL + tx + 16 * j] = fsum2(acc[i][j]);
        }
    } else {
        float* Qs = pool;            // [64][65]
        float* Ws = pool + 4160;     // [64][65]
        const int idx0 = bx - 128;
        const int r0 = (idx0 >> 3) * 64;
        const int h  = idx0 & 7;

        #pragma unroll
        for (int r = 0; r < 4; r++) {
            int idx = t + r * 256;
            int m   = idx >> 4;
            int c4  = (idx & 15) << 2;
            float4 q = *(const float4*)(dQ + (size_t)(r0 + m) * DD + h * 64 + c4);
            Qs[m * 65 + c4 + 0] = q.x; Qs[m * 65 + c4 + 1] = q.y;
            Qs[m * 65 + c4 + 2] = q.z; Qs[m * 65 + c4 + 3] = q.w;
            float4 w = *(const float4*)(We + (size_t)m * DD + h * 64 + c4);
            Ws[m * 65 + c4 + 0] = w.x; Ws[m * 65 + c4 + 1] = w.y;
            Ws[m * 65 + c4 + 2] = w.z; Ws[m * 65 + c4 + 3] = w.w;
        }
        __syncthreads();

        float acc[4][4] = {};
        #pragma unroll
        for (int c = 0; c < 64; c++) {
            float a[4], b[4];
            #pragma unroll
            for (int i = 0; i < 4; i++) a[i] = Qs[(ty + 16 * i) * 65 + c];
            #pragma unroll
            for (int j = 0; j < 4; j++) b[j] = Ws[(tx + 16 * j) * 65 + c];
            #pragma unroll
            for (int i = 0; i < 4; i++)
                #pragma unroll
                for (int j = 0; j < 4; j++)
                    acc[i][j] += a[i] * b[j];
        }

        #pragma unroll
        for (int i = 0; i < 4; i++) {
            int m = r0 + ty + 16 * i;
            #pragma unroll
            for (int j = 0; j < 4; j++)
                dG[((size_t)m * HH + h) * EE + tx + 16 * j] = acc[i][j];
        }
    }
}

// ---------------------------------------------------------------------------
// Softmax v6: cp.async streaming; max-pass removed (scores bounded, masked
// entries exp(-1e9)=0); fast reciprocal divide. 256 threads, all 8 heads.
// ---------------------------------------------------------------------------
__global__ __launch_bounds__(256, 5) void softmax6(
    const float* __restrict__ eptr, const int* __restrict__ adj)
{
    __shared__ float es[128 * 68];
    __shared__ float sS1[8 * 128];
    __shared__ float gT[512];
    __shared__ float aT[1024];
    __shared__ float redS[32];

    const int bq = blockIdx.x;
    const int b  = bq >> 7, q = bq & 127;
    const int t  = threadIdx.x;
    const int lane = t & 31, warp = t >> 5;

    const uint32_t esb  = smem_u32(es);
    const uint32_t s1b  = smem_u32(sS1);

    const float* erow = eptr + (size_t)bq * LL * EE;
    #pragma unroll
    for (int r = 0; r < 8; r++) {
        int idx = t + r * 256;
        int k   = idx >> 4;
        int j4  = (idx & 15) << 2;
        cp16(esb + (uint32_t)(k * 68 + j4) * 4u, erow + k * EE + j4);
    }
    {
        int h  = t >> 5;
        int k4 = (t & 31) << 2;
        cp16(s1b + (uint32_t)(h * 128 + k4) * 4u,
             dS1 + (((size_t)(b * HH + h)) * LL + q) * LL + k4);
    }
    cp_commit();

    #pragma unroll
    for (int i0 = 0; i0 < 2; i0++) {
        int i = t + i0 * 256;
        int h = i >> 6, j = i & 63;
        gT[j * 8 + h] = dG[(size_t)bq * 512 + i];
    }
    const int k  = t & 127;
    const int jh = t >> 7;
    int adjv = 1;
    if (t < 128) adjv = adj[(size_t)bq * LL + k];

    cp_wait<0>();
    __syncthreads();

    // ---- phase A: partial dots ----
    ull acc2[4] = {0, 0, 0, 0};
    #pragma unroll
    for (int j4 = 0; j4 < 8; j4++) {
        float4 ev4 = *(const float4*)(es + k * 68 + jh * 32 + j4 * 4);
        float evv[4] = {ev4.x, ev4.y, ev4.z, ev4.w};
        #pragma unroll
        for (int c = 0; c < 4; c++) {
            int j = jh * 32 + j4 * 4 + c;
            ull ed = pack2(evv[c], evv[c]);
            ulonglong2 g01 = *(const ulonglong2*)(gT + j * 8);
            ulonglong2 g23 = *(const ulonglong2*)(gT + j * 8 + 4);
            fma2(acc2[0], ed, g01.x); fma2(acc2[1], ed, g01.y);
            fma2(acc2[2], ed, g23.x); fma2(acc2[3], ed, g23.y);
        }
    }
    if (jh == 1) {
        *(ulonglong2*)(aT + k * 8)     = make_ulonglong2(acc2[0], acc2[1]);
        *(ulonglong2*)(aT + k * 8 + 4) = make_ulonglong2(acc2[2], acc2[3]);
    }
    __syncthreads();

    // ---- phase B: exp + sum (no max pass; scores bounded) ----
    float p[8];
    if (t < 128) {
        float sv[8];
        ulonglong2 p01 = *(const ulonglong2*)(aT + k * 8);
        ulonglong2 p23 = *(const ulonglong2*)(aT + k * 8 + 4);
        add2(acc2[0], p01.x); add2(acc2[1], p01.y);
        add2(acc2[2], p23.x); add2(acc2[3], p23.y);
        unpack2(acc2[0], sv[0], sv[1]);
        unpack2(acc2[1], sv[2], sv[3]);
        unpack2(acc2[2], sv[4], sv[5]);
        unpack2(acc2[3], sv[6], sv[7]);
        #pragma unroll
        for (int h = 0; h < HH; h++) {
            float s = (sS1[h * 128 + k] + sv[h]) * 0.125f;
            s = (s > 0.f) ? s : 0.2f * s;
            p[h] = (adjv == 0) ? 0.f : __expf(s);
        }
        #pragma unroll
        for (int h = 0; h < HH; h++) {
            float s = p[h];
            #pragma unroll
            for (int o = 16; o > 0; o >>= 1) s += __shfl_xor_sync(0xffffffffu, s, o);
            if (lane == 0) redS[warp * 8 + h] = s;
        }
    }
    __syncthreads();

    if (t < 128) {
        float al[8];
        #pragma unroll
        for (int h = 0; h < HH; h++) {
            float tot = redS[h] + redS[8 + h] + redS[16 + h] + redS[24 + h];
            al[h] = __fdividef(p[h], tot);
            dALPHA[(((size_t)(b * HH + h)) * LL + q) * LL + k] = al[h];
        }
        *(float4*)(aT + k * 8)     = make_float4(al[0], al[1], al[2], al[3]);
        *(float4*)(aT + k * 8 + 4) = make_float4(al[4], al[5], al[6], al[7]);
    }
    __syncthreads();

    // ---- phase C: Wsum ----
    const int ei = t & 63, qt = t >> 6;
    ull w2[4] = {0, 0, 0, 0};
    #pragma unroll 8
    for (int kk = 0; kk < 32; kk++) {
        int kq = qt * 32 + kk;
        float ev = es[kq * 68 + ei];
        ull ed = pack2(ev, ev);
        ulonglong2 a01 = *(const ulonglong2*)(aT + kq * 8);
        ulonglong2 a23 = *(const ulonglong2*)(aT + kq * 8 + 4);
        fma2(w2[0], ed, a01.x); fma2(w2[1], ed, a01.y);
        fma2(w2[2], ed, a23.x); fma2(w2[3], ed, a23.y);
    }
    __syncthreads();

    if (qt == 1) {
        *(ulonglong2*)(aT + ei * 8)       = make_ulonglong2(w2[0], w2[1]);
        *(ulonglong2*)(aT + ei * 8 + 4)   = make_ulonglong2(w2[2], w2[3]);
    } else if (qt == 2) {
        *(ulonglong2*)(aT + 512 + ei * 8)     = make_ulonglong2(w2[0], w2[1]);
        *(ulonglong2*)(aT + 512 + ei * 8 + 4) = make_ulonglong2(w2[2], w2[3]);
    } else if (qt == 3) {
        *(ulonglong2*)(gT + ei * 8)       = make_ulonglong2(w2[0], w2[1]);
        *(ulonglong2*)(gT + ei * 8 + 4)   = make_ulonglong2(w2[2], w2[3]);
    }
    __syncthreads();

    if (qt == 0) {
        ulonglong2 s1a = *(const ulonglong2*)(aT + ei * 8);
        ulonglong2 s1b2 = *(const ulonglong2*)(aT + ei * 8 + 4);
        ulonglong2 s2a = *(const ulonglong2*)(aT + 512 + ei * 8);
        ulonglong2 s2b = *(const ulonglong2*)(aT + 512 + ei * 8 + 4);
        ulonglong2 s3a = *(const ulonglong2*)(gT + ei * 8);
        ulonglong2 s3b = *(const ulonglong2*)(gT + ei * 8 + 4);
        add2(w2[0], s1a.x); add2(w2[1], s1a.y); add2(w2[2], s1b2.x); add2(w2[3], s1b2.y);
        add2(w2[0], s2a.x); add2(w2[1], s2a.y); add2(w2[2], s2b.x);  add2(w2[3], s2b.y);
        add2(w2[0], s3a.x); add2(w2[1], s3a.y); add2(w2[2], s3b.x);  add2(w2[3], s3b.y);
        float w[8];
        unpack2(w2[0], w[0], w[1]); unpack2(w2[1], w[2], w[3]);
        unpack2(w2[2], w[4], w[5]); unpack2(w2[3], w[6], w[7]);
        #pragma unroll
        for (int h = 0; h < HH; h++)
            dWsum[(((size_t)(b * HH + h)) * LL + q) * EE + ei] = w[h];
    }
}

// ---------------------------------------------------------------------------
// LayerNorm + ReLU per row of 512
// ---------------------------------------------------------------------------
__global__ __launch_bounds__(256) void ln_kernel(
    const float* __restrict__ gamma, const float* __restrict__ beta,
    float* __restrict__ out)
{
    const int r = blockIdx.x;
    const int t = threadIdx.x;
    const int lane = t & 31, warp = t >> 5;

    float v0 = dFFN[(size_t)r * DD + t];
    float v1 = dFFN[(size_t)r * DD + 256 + t];
    float s  = v0 + v1;
    float sq = v0 * v0 + v1 * v1;

    __shared__ float rs[8], rq[8];
    __shared__ float mu_s, rstd_s;
    #pragma unroll
    for (int o = 16; o > 0; o >>= 1) {
        s  += __shfl_xor_sync(0xffffffffu, s, o);
        sq += __shfl_xor_sync(0xffffffffu, sq, o);
    }
    if (lane == 0) { rs[warp] = s; rq[warp] = sq; }
    __syncthreads();
    if (t == 0) {
        float S = 0.f, Q2 = 0.f;
        #pragma unroll
        for (int w = 0; w < 8; w++) { S += rs[w]; Q2 += rq[w]; }
        float mu  = S / 512.f;
        float var = Q2 / 512.f - mu * mu;
        mu_s = mu;
        rstd_s = rsqrtf(var + 1e-5f);
    }
    __syncthreads();
    float mu = mu_s, rstd = rstd_s;

    float y0 = (v0 - mu) * rstd * gamma[t]       + beta[t];
    float y1 = (v1 - mu) * rstd * gamma[256 + t] + beta[256 + t];
    out[(size_t)r * DD + t]       = fmaxf(y0, 0.f);
    out[(size_t)r * DD + 256 + t] = fmaxf(y1, 0.f);
}

// ---------------------------------------------------------------------------
extern "C" void kernel_launch(void* const* d_in, const int* in_sizes, int n_in,
                              void* d_out, int out_size)
{
    const float* x     = (const float*)d_in[0];
    const int*   adj   = (const int*)  d_in[1];
    const float* e     = (const float*)d_in[2];
    const float* Wq    = (const float*)d_in[3];
    const float* Wkv   = (const float*)d_in[4];
    const float* We    = (const float*)d_in[5];
    const float* Wf    = (const float*)d_in[6];
    const float* bf    = (const float*)d_in[7];
    const float* gamma = (const float*)d_in[8];
    const float* beta  = (const float*)d_in[9];
    float* out = (float*)d_out;

    float *pQ, *pKV, *pATTN, *pFFN;
    cudaGetSymbolAddress((void**)&pQ,    dQ);
    cudaGetSymbolAddress((void**)&pKV,   dKV);
    cudaGetSymbolAddress((void**)&pATTN, dATTN);
    cudaGetSymbolAddress((void**)&pFFN,  dFFN);

    // 1. Q = x@Wq, KV = x@Wkv  (512 CTAs, 4-stage pipeline)
    gemm_ca<<<dim3(DD/64, BL/32, 2), 128>>>(x, Wq, pQ, Wkv, pKV, nullptr, DD, DD);
    // 2+3. S1 and g merged
    s1g_kernel<<<256, 256>>>(We);
    // 4. softmax (no max pass)
    softmax6<<<BL, 256>>>(e, adj);
    // 5. attention output (256 CTAs, 4-stage)
    attn_ca<<<dim3(BB*HH, 4), 128>>>(We);
    // 6. FFN GEMM with bias (256 CTAs, 4-stage)
    gemm_ca<<<dim3(DD/64, BL/32, 1), 128>>>(pATTN, Wf, pFFN, nullptr, nullptr, bf, DD, DD);
    // 7. LayerNorm + ReLU
    ln_kernel<<<BL, 256>>>(gamma, beta, out);
}

// round 12
// speedup vs baseline: 1.0286x; 1.0286x over previous
#include <cuda_runtime.h>
#include <math.h>
#include <stdint.h>

#define BB 8
#define LL 128
#define DD 512
#define EE 64
#define HH 8
#define BL (BB*LL)   // 1024

typedef unsigned long long ull;

__device__ __forceinline__ void fma2(ull &acc, ull a, ull b) {
    asm("fma.rn.f32x2 %0, %1, %2, %0;" : "+l"(acc) : "l"(a), "l"(b));
}
__device__ __forceinline__ void add2(ull &a, ull b) {
    asm("add.rn.f32x2 %0, %0, %1;" : "+l"(a) : "l"(b));
}
__device__ __forceinline__ ull pack2(float x, float y) {
    ull r; asm("mov.b64 %0, {%1,%2};" : "=l"(r) : "f"(x), "f"(y)); return r;
}
__device__ __forceinline__ void unpack2(ull v, float &x, float &y) {
    asm("mov.b64 {%0,%1}, %2;" : "=f"(x), "=f"(y) : "l"(v));
}
__device__ __forceinline__ float fsum2(ull v) {
    float x, y; unpack2(v, x, y); return x + y;
}

// cp.async helpers
__device__ __forceinline__ uint32_t smem_u32(const void* p) {
    uint32_t a;
    asm("{ .reg .u64 t; cvta.to.shared.u64 t, %1; cvt.u32.u64 %0, t; }" : "=r"(a) : "l"(p));
    return a;
}
__device__ __forceinline__ void cp16(uint32_t d, const void* s) {
    asm volatile("cp.async.ca.shared.global [%0], [%1], 16;" :: "r"(d), "l"(s));
}
__device__ __forceinline__ void cp_commit() {
    asm volatile("cp.async.commit_group;" ::: "memory");
}
template<int N> __device__ __forceinline__ void cp_wait() {
    asm volatile("cp.async.wait_group %0;" :: "n"(N) : "memory");
}

// Scratch
__device__ float dQ[BL*DD];
__device__ float dKV[BL*DD];
__device__ float dG[BL*HH*EE];           // [bq][h][e]
__device__ float dS1[BB*HH*LL*LL];       // [bh][q][k]
__device__ float dALPHA[BB*HH*LL*LL];    // [bh][q][k]
__device__ float dWsum[BB*HH*LL*EE];     // [bh][q][e]
__device__ float dATTN[BL*DD];
__device__ float dFFN[BL*DD];

// ---------------------------------------------------------------------------
// Split-K cp.async f32x2 GEMM: 64x64 tile, 128 threads, 2-stage (R9 shape).
// blockIdx.z = mat * nsplit + sp. Each split does K2 of the reduction and
// atomicAdds into C (zeroed beforehand). Bias added by split 0 only.
// ---------------------------------------------------------------------------
__global__ __launch_bounds__(128) void gemm_ca(
    const float* __restrict__ A,
    const float* __restrict__ B0, float* __restrict__ C0,
    const float* __restrict__ B1, float* __restrict__ C1,
    const float* __restrict__ bias, int lda, int K2, int N, int nsplit)
{
    __shared__ float As[2][64*36];
    __shared__ float Bs[2][32*64];

    const int mat = blockIdx.z / nsplit;
    const int sp  = blockIdx.z % nsplit;
    const float* Bm = mat ? B1 : B0;
    float*       Cm = mat ? C1 : C0;
    const int kbase = sp * K2;

    const int t  = threadIdx.x;
    const int tx = t & 15, ty = t >> 4;
    const int m0 = blockIdx.y * 64, n0 = blockIdx.x * 64;

    const uint32_t asb = smem_u32(&As[0][0]);
    const uint32_t bsb = smem_u32(&Bs[0][0]);

    ull acc[8][2] = {};

    #define ISSUE_TILE(buf, k0) do {                                            \
        _Pragma("unroll")                                                       \
        for (int r = 0; r < 4; r++) {                                           \
            int idx = t + r * 128;                                              \
            int m = idx >> 3, k4 = (idx & 7) << 2;                              \
            cp16(asb + (buf) * 9216u + (uint32_t)(m * 36 + k4) * 4u,            \
                 A + (size_t)(m0 + m) * lda + (k0) + k4);                       \
        }                                                                       \
        _Pragma("unroll")                                                       \
        for (int r = 0; r < 4; r++) {                                           \
            int idx = t + r * 128;                                              \
            int kk = idx >> 4, n4 = (idx & 15) << 2;                            \
            cp16(bsb + (buf) * 8192u + (uint32_t)(kk * 64 + n4) * 4u,           \
                 Bm + (size_t)((k0) + kk) * N + n0 + n4);                       \
        }                                                                       \
        cp_commit();                                                            \
    } while (0)

    ISSUE_TILE(0, kbase);

    const int NT = K2 / 32;
    int buf = 0;
    for (int kt = 0; kt < NT; kt++) {
        if (kt + 1 < NT) { ISSUE_TILE(buf ^ 1, kbase + (kt + 1) * 32); cp_wait<1>(); }
        else             { cp_wait<0>(); }
        __syncthreads();

        #pragma unroll 4
        for (int kk = 0; kk < 32; kk += 2) {
            ull bp00 = *(const ull*)&Bs[buf][kk * 64 + tx * 2];
            ull bp01 = *(const ull*)&Bs[buf][kk * 64 + tx * 2 + 32];
            ull bp10 = *(const ull*)&Bs[buf][(kk + 1) * 64 + tx * 2];
            ull bp11 = *(const ull*)&Bs[buf][(kk + 1) * 64 + tx * 2 + 32];
            #pragma unroll
            for (int i = 0; i < 8; i++) {
                float2 af = *(const float2*)&As[buf][(ty * 8 + i) * 36 + kk];
                ull ad0 = pack2(af.x, af.x);
                ull ad1 = pack2(af.y, af.y);
                fma2(acc[i][0], ad0, bp00);
                fma2(acc[i][1], ad0, bp01);
                fma2(acc[i][0], ad1, bp10);
                fma2(acc[i][1], ad1, bp11);
            }
        }
        __syncthreads();
        buf ^= 1;
    }
    #undef ISSUE_TILE

    #pragma unroll
    for (int i = 0; i < 8; i++) {
        int m = m0 + ty * 8 + i;
        float x0, x1, y0, y1;
        unpack2(acc[i][0], x0, x1);
        unpack2(acc[i][1], y0, y1);
        int nA = n0 + tx * 2, nB = nA + 32;
        if (bias && sp == 0) {
            x0 += bias[nA]; x1 += bias[nA + 1];
            y0 += bias[nB]; y1 += bias[nB + 1];
        }
        float* crow = Cm + (size_t)m * N;
        atomicAdd(crow + nA,     x0);
        atomicAdd(crow + nA + 1, x1);
        atomicAdd(crow + nB,     y0);
        atomicAdd(crow + nB + 1, y1);
    }
}

// ---------------------------------------------------------------------------
// attn split-K cp.async GEMM: 64x64 tiles, grid (64, 2, 2); K=192 -> 2x96.
// C = [alpha | Wsum] @ [KV_h ; We_h], atomicAdd into zeroed dATTN.
// ---------------------------------------------------------------------------
__global__ __launch_bounds__(128) void attn_ca(const float* __restrict__ We)
{
    __shared__ float As[2][64*36];
    __shared__ float Bs[2][32*64];

    const int bh = blockIdx.x, mh = blockIdx.y, sp = blockIdx.z;
    const int b  = bh >> 3, h = bh & 7;
    const int t  = threadIdx.x;
    const int tx = t & 15, ty = t >> 4;
    const int kbase = sp * 96;

    const uint32_t asb = smem_u32(&As[0][0]);
    const uint32_t bsb = smem_u32(&Bs[0][0]);

    ull acc[8][2] = {};

    #define ISSUE_ATTN(buf, k0) do {                                            \
        _Pragma("unroll")                                                       \
        for (int r = 0; r < 4; r++) {                                           \
            int idx = t + r * 128;                                              \
            int m = idx >> 3, k4 = (idx & 7) << 2;                              \
            size_t row = (size_t)bh * LL + mh * 64 + m;                         \
            const float* src = ((k0) < 128)                                     \
                ? (dALPHA + row * LL + (k0) + k4)                               \
                : (dWsum  + row * EE + ((k0) - 128) + k4);                      \
            cp16(asb + (buf) * 9216u + (uint32_t)(m * 36 + k4) * 4u, src);      \
        }                                                                       \
        _Pragma("unroll")                                                       \
        for (int r = 0; r < 4; r++) {                                           \
            int idx = t + r * 128;                                              \
            int kk = idx >> 4, n4 = (idx & 15) << 2;                            \
            int kg = (k0) + kk;                                                 \
            const float* src = (kg < 128)                                       \
                ? (dKV + (size_t)(b * LL + kg) * DD + h * 64 + n4)              \
                : (We  + (size_t)(kg - 128) * DD + h * 64 + n4);                \
            cp16(bsb + (buf) * 8192u + (uint32_t)(kk * 64 + n4) * 4u, src);     \
        }                                                                       \
        cp_commit();                                                            \
    } while (0)

    ISSUE_ATTN(0, kbase);

    const int NT = 3;   // 96 per split
    int buf = 0;
    for (int kt = 0; kt < NT; kt++) {
        if (kt + 1 < NT) { ISSUE_ATTN(buf ^ 1, kbase + (kt + 1) * 32); cp_wait<1>(); }
        else             { cp_wait<0>(); }
        __syncthreads();

        #pragma unroll 4
        for (int kk = 0; kk < 32; kk += 2) {
            ull bp00 = *(const ull*)&Bs[buf][kk * 64 + tx * 2];
            ull bp01 = *(const ull*)&Bs[buf][kk * 64 + tx * 2 + 32];
            ull bp10 = *(const ull*)&Bs[buf][(kk + 1) * 64 + tx * 2];
            ull bp11 = *(const ull*)&Bs[buf][(kk + 1) * 64 + tx * 2 + 32];
            #pragma unroll
            for (int i = 0; i < 8; i++) {
                float2 af = *(const float2*)&As[buf][(ty * 8 + i) * 36 + kk];
                ull ad0 = pack2(af.x, af.x);
                ull ad1 = pack2(af.y, af.y);
                fma2(acc[i][0], ad0, bp00);
                fma2(acc[i][1], ad0, bp01);
                fma2(acc[i][0], ad1, bp10);
                fma2(acc[i][1], ad1, bp11);
            }
        }
        __syncthreads();
        buf ^= 1;
    }
    #undef ISSUE_ATTN

    #pragma unroll
    for (int i = 0; i < 8; i++) {
        int m = mh * 64 + ty * 8 + i;
        float* crow = dATTN + ((size_t)(b * LL) + m) * DD + h * 64;
        float x0, x1, y0, y1;
        unpack2(acc[i][0], x0, x1);
        unpack2(acc[i][1], y0, y1);
        atomicAdd(crow + tx * 2,          x0);
        atomicAdd(crow + tx * 2 + 1,      x1);
        atomicAdd(crow + tx * 2 + 32,     y0);
        atomicAdd(crow + tx * 2 + 33,     y1);
    }
}

// ---------------------------------------------------------------------------
// Merged s1 + g kernel (proven): 256 blocks x 256 threads.
// ---------------------------------------------------------------------------
__global__ __launch_bounds__(256) void s1g_kernel(const float* __restrict__ We)
{
    __shared__ float pool[8320];

    const int bx = blockIdx.x;
    const int t  = threadIdx.x;
    const int tx = t & 15, ty = t >> 4;

    if (bx < 128) {
        float* Qs = pool;            // [64][34]
        float* Ks = pool + 2176;     // [128][34]
        const int bh = bx >> 1, mh = bx & 1;
        const int b  = bh >> 3, h = bh & 7;

        ull acc[4][8] = {};

        for (int c0 = 0; c0 < 64; c0 += 32) {
            #pragma unroll
            for (int r = 0; r < 2; r++) {
                int idx = t + r * 256;
                int m   = idx >> 3;
                int c4  = (idx & 7) << 2;
                float4 v = *(const float4*)(dQ + (size_t)(b * LL + mh * 64 + m) * DD + h * 64 + c0 + c4);
                *(float2*)(Qs + m * 34 + c4)     = make_float2(v.x, v.y);
                *(float2*)(Qs + m * 34 + c4 + 2) = make_float2(v.z, v.w);
            }
            #pragma unroll
            for (int r = 0; r < 4; r++) {
                int idx = t + r * 256;
                int n   = idx >> 3;
                int c4  = (idx & 7) << 2;
                float4 v = *(const float4*)(dKV + (size_t)(b * LL + n) * DD + h * 64 + c0 + c4);
                *(float2*)(Ks + n * 34 + c4)     = make_float2(v.x, v.y);
                *(float2*)(Ks + n * 34 + c4 + 2) = make_float2(v.z, v.w);
            }
            __syncthreads();

            #pragma unroll
            for (int cc = 0; cc < 32; cc += 2) {
                ull a[4], b2[8];
                #pragma unroll
                for (int i = 0; i < 4; i++) a[i]  = *(const ull*)(Qs + (ty * 4 + i) * 34 + cc);
                #pragma unroll
                for (int j = 0; j < 8; j++) b2[j] = *(const ull*)(Ks + (tx + 16 * j) * 34 + cc);
                #pragma unroll
                for (int i = 0; i < 4; i++)
                    #pragma unroll
                    for (int j = 0; j < 8; j++)
                        fma2(acc[i][j], a[i], b2[j]);
            }
            __syncthreads();
        }

        #pragma unroll
        for (int i = 0; i < 4; i++) {
            int m = mh * 64 + ty * 4 + i;
            #pragma unroll
            for (int j = 0; j < 8; j++)
                dS1[((size_t)bh * LL + m) * LL + tx + 16 * j] = fsum2(acc[i][j]);
        }
    } else {
        float* Qs = pool;            // [64][65]
        float* Ws = pool + 4160;     // [64][65]
        const int idx0 = bx - 128;
        const int r0 = (idx0 >> 3) * 64;
        const int h  = idx0 & 7;

        #pragma unroll
        for (int r = 0; r < 4; r++) {
            int idx = t + r * 256;
            int m   = idx >> 4;
            int c4  = (idx & 15) << 2;
            float4 q = *(const float4*)(dQ + (size_t)(r0 + m) * DD + h * 64 + c4);
            Qs[m * 65 + c4 + 0] = q.x; Qs[m * 65 + c4 + 1] = q.y;
            Qs[m * 65 + c4 + 2] = q.z; Qs[m * 65 + c4 + 3] = q.w;
            float4 w = *(const float4*)(We + (size_t)m * DD + h * 64 + c4);
            Ws[m * 65 + c4 + 0] = w.x; Ws[m * 65 + c4 + 1] = w.y;
            Ws[m * 65 + c4 + 2] = w.z; Ws[m * 65 + c4 + 3] = w.w;
        }
        __syncthreads();

        float acc[4][4] = {};
        #pragma unroll
        for (int c = 0; c < 64; c++) {
            float a[4], b[4];
            #pragma unroll
            for (int i = 0; i < 4; i++) a[i] = Qs[(ty + 16 * i) * 65 + c];
            #pragma unroll
            for (int j = 0; j < 4; j++) b[j] = Ws[(tx + 16 * j) * 65 + c];
            #pragma unroll
            for (int i = 0; i < 4; i++)
                #pragma unroll
                for (int j = 0; j < 4; j++)
                    acc[i][j] += a[i] * b[j];
        }

        #pragma unroll
        for (int i = 0; i < 4; i++) {
            int m = r0 + ty + 16 * i;
            #pragma unroll
            for (int j = 0; j < 4; j++)
                dG[((size_t)m * HH + h) * EE + tx + 16 * j] = acc[i][j];
        }
    }
}

// ---------------------------------------------------------------------------
// Softmax v6: cp.async streaming; no max pass; fast divide. 256 threads.
// ---------------------------------------------------------------------------
__global__ __launch_bounds__(256, 5) void softmax6(
    const float* __restrict__ eptr, const int* __restrict__ adj)
{
    __shared__ float es[128 * 68];
    __shared__ float sS1[8 * 128];
    __shared__ float gT[512];
    __shared__ float aT[1024];
    __shared__ float redS[32];

    const int bq = blockIdx.x;
    const int b  = bq >> 7, q = bq & 127;
    const int t  = threadIdx.x;
    const int lane = t & 31, warp = t >> 5;

    const uint32_t esb  = smem_u32(es);
    const uint32_t s1b  = smem_u32(sS1);

    const float* erow = eptr + (size_t)bq * LL * EE;
    #pragma unroll
    for (int r = 0; r < 8; r++) {
        int idx = t + r * 256;
        int k   = idx >> 4;
        int j4  = (idx & 15) << 2;
        cp16(esb + (uint32_t)(k * 68 + j4) * 4u, erow + k * EE + j4);
    }
    {
        int h  = t >> 5;
        int k4 = (t & 31) << 2;
        cp16(s1b + (uint32_t)(h * 128 + k4) * 4u,
             dS1 + (((size_t)(b * HH + h)) * LL + q) * LL + k4);
    }
    cp_commit();

    #pragma unroll
    for (int i0 = 0; i0 < 2; i0++) {
        int i = t + i0 * 256;
        int h = i >> 6, j = i & 63;
        gT[j * 8 + h] = dG[(size_t)bq * 512 + i];
    }
    const int k  = t & 127;
    const int jh = t >> 7;
    int adjv = 1;
    if (t < 128) adjv = adj[(size_t)bq * LL + k];

    cp_wait<0>();
    __syncthreads();

    ull acc2[4] = {0, 0, 0, 0};
    #pragma unroll
    for (int j4 = 0; j4 < 8; j4++) {
        float4 ev4 = *(const float4*)(es + k * 68 + jh * 32 + j4 * 4);
        float evv[4] = {ev4.x, ev4.y, ev4.z, ev4.w};
        #pragma unroll
        for (int c = 0; c < 4; c++) {
            int j = jh * 32 + j4 * 4 + c;
            ull ed = pack2(evv[c], evv[c]);
            ulonglong2 g01 = *(const ulonglong2*)(gT + j * 8);
            ulonglong2 g23 = *(const ulonglong2*)(gT + j * 8 + 4);
            fma2(acc2[0], ed, g01.x); fma2(acc2[1], ed, g01.y);
            fma2(acc2[2], ed, g23.x); fma2(acc2[3], ed, g23.y);
        }
    }
    if (jh == 1) {
        *(ulonglong2*)(aT + k * 8)     = make_ulonglong2(acc2[0], acc2[1]);
        *(ulonglong2*)(aT + k * 8 + 4) = make_ulonglong2(acc2[2], acc2[3]);
    }
    __syncthreads();

    float p[8];
    if (t < 128) {
        float sv[8];
        ulonglong2 p01 = *(const ulonglong2*)(aT + k * 8);
        ulonglong2 p23 = *(const ulonglong2*)(aT + k * 8 + 4);
        add2(acc2[0], p01.x); add2(acc2[1], p01.y);
        add2(acc2[2], p23.x); add2(acc2[3], p23.y);
        unpack2(acc2[0], sv[0], sv[1]);
        unpack2(acc2[1], sv[2], sv[3]);
        unpack2(acc2[2], sv[4], sv[5]);
        unpack2(acc2[3], sv[6], sv[7]);
        #pragma unroll
        for (int h = 0; h < HH; h++) {
            float s = (sS1[h * 128 + k] + sv[h]) * 0.125f;
            s = (s > 0.f) ? s : 0.2f * s;
            p[h] = (adjv == 0) ? 0.f : __expf(s);
        }
        #pragma unroll
        for (int h = 0; h < HH; h++) {
            float s = p[h];
            #pragma unroll
            for (int o = 16; o > 0; o >>= 1) s += __shfl_xor_sync(0xffffffffu, s, o);
            if (lane == 0) redS[warp * 8 + h] = s;
        }
    }
    __syncthreads();

    if (t < 128) {
        float al[8];
        #pragma unroll
        for (int h = 0; h < HH; h++) {
            float tot = redS[h] + redS[8 + h] + redS[16 + h] + redS[24 + h];
            al[h] = __fdividef(p[h], tot);
            dALPHA[(((size_t)(b * HH + h)) * LL + q) * LL + k] = al[h];
        }
        *(float4*)(aT + k * 8)     = make_float4(al[0], al[1], al[2], al[3]);
        *(float4*)(aT + k * 8 + 4) = make_float4(al[4], al[5], al[6], al[7]);
    }
    __syncthreads();

    const int ei = t & 63, qt = t >> 6;
    ull w2[4] = {0, 0, 0, 0};
    #pragma unroll 8
    for (int kk = 0; kk < 32; kk++) {
        int kq = qt * 32 + kk;
        float ev = es[kq * 68 + ei];
        ull ed = pack2(ev, ev);
        ulonglong2 a01 = *(const ulonglong2*)(aT + kq * 8);
        ulonglong2 a23 = *(const ulonglong2*)(aT + kq * 8 + 4);
        fma2(w2[0], ed, a01.x); fma2(w2[1], ed, a01.y);
        fma2(w2[2], ed, a23.x); fma2(w2[3], ed, a23.y);
    }
    __syncthreads();

    if (qt == 1) {
        *(ulonglong2*)(aT + ei * 8)       = make_ulonglong2(w2[0], w2[1]);
        *(ulonglong2*)(aT + ei * 8 + 4)   = make_ulonglong2(w2[2], w2[3]);
    } else if (qt == 2) {
        *(ulonglong2*)(aT + 512 + ei * 8)     = make_ulonglong2(w2[0], w2[1]);
        *(ulonglong2*)(aT + 512 + ei * 8 + 4) = make_ulonglong2(w2[2], w2[3]);
    } else if (qt == 3) {
        *(ulonglong2*)(gT + ei * 8)       = make_ulonglong2(w2[0], w2[1]);
        *(ulonglong2*)(gT + ei * 8 + 4)   = make_ulonglong2(w2[2], w2[3]);
    }
    __syncthreads();

    if (qt == 0) {
        ulonglong2 s1a = *(const ulonglong2*)(aT + ei * 8);
        ulonglong2 s1b2 = *(const ulonglong2*)(aT + ei * 8 + 4);
        ulonglong2 s2a = *(const ulonglong2*)(aT + 512 + ei * 8);
        ulonglong2 s2b = *(const ulonglong2*)(aT + 512 + ei * 8 + 4);
        ulonglong2 s3a = *(const ulonglong2*)(gT + ei * 8);
        ulonglong2 s3b = *(const ulonglong2*)(gT + ei * 8 + 4);
        add2(w2[0], s1a.x); add2(w2[1], s1a.y); add2(w2[2], s1b2.x); add2(w2[3], s1b2.y);
        add2(w2[0], s2a.x); add2(w2[1], s2a.y); add2(w2[2], s2b.x);  add2(w2[3], s2b.y);
        add2(w2[0], s3a.x); add2(w2[1], s3a.y); add2(w2[2], s3b.x);  add2(w2[3], s3b.y);
        float w[8];
        unpack2(w2[0], w[0], w[1]); unpack2(w2[1], w[2], w[3]);
        unpack2(w2[2], w[4], w[5]); unpack2(w2[3], w[6], w[7]);
        #pragma unroll
        for (int h = 0; h < HH; h++)
            dWsum[(((size_t)(b * HH + h)) * LL + q) * EE + ei] = w[h];
    }
}

// ---------------------------------------------------------------------------
// LayerNorm + ReLU per row of 512
// ---------------------------------------------------------------------------
__global__ __launch_bounds__(256) void ln_kernel(
    const float* __restrict__ gamma, const float* __restrict__ beta,
    float* __restrict__ out)
{
    const int r = blockIdx.x;
    const int t = threadIdx.x;
    const int lane = t & 31, warp = t >> 5;

    float v0 = dFFN[(size_t)r * DD + t];
    float v1 = dFFN[(size_t)r * DD + 256 + t];
    float s  = v0 + v1;
    float sq = v0 * v0 + v1 * v1;

    __shared__ float rs[8], rq[8];
    __shared__ float mu_s, rstd_s;
    #pragma unroll
    for (int o = 16; o > 0; o >>= 1) {
        s  += __shfl_xor_sync(0xffffffffu, s, o);
        sq += __shfl_xor_sync(0xffffffffu, sq, o);
    }
    if (lane == 0) { rs[warp] = s; rq[warp] = sq; }
    __syncthreads();
    if (t == 0) {
        float S = 0.f, Q2 = 0.f;
        #pragma unroll
        for (int w = 0; w < 8; w++) { S += rs[w]; Q2 += rq[w]; }
        float mu  = S / 512.f;
        float var = Q2 / 512.f - mu * mu;
        mu_s = mu;
        rstd_s = rsqrtf(var + 1e-5f);
    }
    __syncthreads();
    float mu = mu_s, rstd = rstd_s;

    float y0 = (v0 - mu) * rstd * gamma[t]       + beta[t];
    float y1 = (v1 - mu) * rstd * gamma[256 + t] + beta[256 + t];
    out[(size_t)r * DD + t]       = fmaxf(y0, 0.f);
    out[(size_t)r * DD + 256 + t] = fmaxf(y1, 0.f);
}

// ---------------------------------------------------------------------------
extern "C" void kernel_launch(void* const* d_in, const int* in_sizes, int n_in,
                              void* d_out, int out_size)
{
    const float* x     = (const float*)d_in[0];
    const int*   adj   = (const int*)  d_in[1];
    const float* e     = (const float*)d_in[2];
    const float* Wq    = (const float*)d_in[3];
    const float* Wkv   = (const float*)d_in[4];
    const float* We    = (const float*)d_in[5];
    const float* Wf    = (const float*)d_in[6];
    const float* bf    = (const float*)d_in[7];
    const float* gamma = (const float*)d_in[8];
    const float* beta  = (const float*)d_in[9];
    float* out = (float*)d_out;

    float *pQ, *pKV, *pATTN, *pFFN;
    cudaGetSymbolAddress((void**)&pQ,    dQ);
    cudaGetSymbolAddress((void**)&pKV,   dKV);
    cudaGetSymbolAddress((void**)&pATTN, dATTN);
    cudaGetSymbolAddress((void**)&pFFN,  dFFN);

    // 0. zero split-K accumulation targets (graph-capturable memset nodes)
    cudaMemsetAsync(pQ,    0, (size_t)BL * DD * sizeof(float));
    cudaMemsetAsync(pKV,   0, (size_t)BL * DD * sizeof(float));
    cudaMemsetAsync(pATTN, 0, (size_t)BL * DD * sizeof(float));
    cudaMemsetAsync(pFFN,  0, (size_t)BL * DD * sizeof(float));

    // 1. Q = x@Wq, KV = x@Wkv  (split-K 2: 512 CTAs, 8 tiles each)
    gemm_ca<<<dim3(DD/64, BL/64, 4), 128>>>(x, Wq, pQ, Wkv, pKV, nullptr,
                                            DD, DD/2, DD, 2);
    // 2+3. S1 and g merged
    s1g_kernel<<<256, 256>>>(We);
    // 4. softmax
    softmax6<<<BL, 256>>>(e, adj);
    // 5. attention output (split-K 2: 256 CTAs, 3 tiles each)
    attn_ca<<<dim3(BB*HH, 2, 2), 128>>>(We);
    // 6. FFN GEMM with bias (split-K 2: 256 CTAs)
    gemm_ca<<<dim3(DD/64, BL/64, 2), 128>>>(pATTN, Wf, pFFN, nullptr, nullptr, bf,
                                            DD, DD/2, DD, 2);
    // 7. LayerNorm + ReLU
    ln_kernel<<<BL, 256>>>(gamma, beta, out);
}

// round 13
// speedup vs baseline: 1.0581x; 1.0287x over previous
#include <cuda_runtime.h>
#include <math.h>
#include <stdint.h>

#define BB 8
#define LL 128
#define DD 512
#define EE 64
#define HH 8
#define BL (BB*LL)   // 1024

typedef unsigned long long ull;

__device__ __forceinline__ void fma2(ull &acc, ull a, ull b) {
    asm("fma.rn.f32x2 %0, %1, %2, %0;" : "+l"(acc) : "l"(a), "l"(b));
}
__device__ __forceinline__ void add2(ull &a, ull b) {
    asm("add.rn.f32x2 %0, %0, %1;" : "+l"(a) : "l"(b));
}
__device__ __forceinline__ ull pack2(float x, float y) {
    ull r; asm("mov.b64 %0, {%1,%2};" : "=l"(r) : "f"(x), "f"(y)); return r;
}
__device__ __forceinline__ void unpack2(ull v, float &x, float &y) {
    asm("mov.b64 {%0,%1}, %2;" : "=f"(x), "=f"(y) : "l"(v));
}
__device__ __forceinline__ float fsum2(ull v) {
    float x, y; unpack2(v, x, y); return x + y;
}

// cp.async helpers
__device__ __forceinline__ uint32_t smem_u32(const void* p) {
    uint32_t a;
    asm("{ .reg .u64 t; cvta.to.shared.u64 t, %1; cvt.u32.u64 %0, t; }" : "=r"(a) : "l"(p));
    return a;
}
__device__ __forceinline__ void cp16(uint32_t d, const void* s) {
    asm volatile("cp.async.ca.shared.global [%0], [%1], 16;" :: "r"(d), "l"(s));
}
__device__ __forceinline__ void cp_commit() {
    asm volatile("cp.async.commit_group;" ::: "memory");
}
template<int N> __device__ __forceinline__ void cp_wait() {
    asm volatile("cp.async.wait_group %0;" :: "n"(N) : "memory");
}

// Scratch — split-K accumulation targets live in ONE array (single memset node)
__device__ float dACC[4 * BL * DD];      // [dQ | dKV | dATTN | dFFN]
#define dQ_P    (dACC)
#define dKV_P   (dACC + (size_t)BL * DD)
#define dATTN_P (dACC + (size_t)2 * BL * DD)
#define dFFN_P  (dACC + (size_t)3 * BL * DD)

__device__ float dG[BL*HH*EE];           // [bq][h][e]
__device__ float dS1[BB*HH*LL*LL];       // [bh][q][k]
__device__ float dALPHA[BB*HH*LL*LL];    // [bh][q][k]
__device__ float dWsum[BB*HH*LL*EE];     // [bh][q][e]

// ---------------------------------------------------------------------------
// Split-K cp.async f32x2 GEMM: 64x64 tile, 128 threads, 2-stage (R12 proven).
// ---------------------------------------------------------------------------
__global__ __launch_bounds__(128) void gemm_ca(
    const float* __restrict__ A,
    const float* __restrict__ B0, float* __restrict__ C0,
    const float* __restrict__ B1, float* __restrict__ C1,
    const float* __restrict__ bias, int lda, int K2, int N, int nsplit)
{
    __shared__ float As[2][64*36];
    __shared__ float Bs[2][32*64];

    const int mat = blockIdx.z / nsplit;
    const int sp  = blockIdx.z % nsplit;
    const float* Bm = mat ? B1 : B0;
    float*       Cm = mat ? C1 : C0;
    const int kbase = sp * K2;

    const int t  = threadIdx.x;
    const int tx = t & 15, ty = t >> 4;
    const int m0 = blockIdx.y * 64, n0 = blockIdx.x * 64;

    const uint32_t asb = smem_u32(&As[0][0]);
    const uint32_t bsb = smem_u32(&Bs[0][0]);

    ull acc[8][2] = {};

    #define ISSUE_TILE(buf, k0) do {                                            \
        _Pragma("unroll")                                                       \
        for (int r = 0; r < 4; r++) {                                           \
            int idx = t + r * 128;                                              \
            int m = idx >> 3, k4 = (idx & 7) << 2;                              \
            cp16(asb + (buf) * 9216u + (uint32_t)(m * 36 + k4) * 4u,            \
                 A + (size_t)(m0 + m) * lda + (k0) + k4);                       \
        }                                                                       \
        _Pragma("unroll")                                                       \
        for (int r = 0; r < 4; r++) {                                           \
            int idx = t + r * 128;                                              \
            int kk = idx >> 4, n4 = (idx & 15) << 2;                            \
            cp16(bsb + (buf) * 8192u + (uint32_t)(kk * 64 + n4) * 4u,           \
                 Bm + (size_t)((k0) + kk) * N + n0 + n4);                       \
        }                                                                       \
        cp_commit();                                                            \
    } while (0)

    ISSUE_TILE(0, kbase);

    const int NT = K2 / 32;
    int buf = 0;
    for (int kt = 0; kt < NT; kt++) {
        if (kt + 1 < NT) { ISSUE_TILE(buf ^ 1, kbase + (kt + 1) * 32); cp_wait<1>(); }
        else             { cp_wait<0>(); }
        __syncthreads();

        #pragma unroll 4
        for (int kk = 0; kk < 32; kk += 2) {
            ull bp00 = *(const ull*)&Bs[buf][kk * 64 + tx * 2];
            ull bp01 = *(const ull*)&Bs[buf][kk * 64 + tx * 2 + 32];
            ull bp10 = *(const ull*)&Bs[buf][(kk + 1) * 64 + tx * 2];
            ull bp11 = *(const ull*)&Bs[buf][(kk + 1) * 64 + tx * 2 + 32];
            #pragma unroll
            for (int i = 0; i < 8; i++) {
                float2 af = *(const float2*)&As[buf][(ty * 8 + i) * 36 + kk];
                ull ad0 = pack2(af.x, af.x);
                ull ad1 = pack2(af.y, af.y);
                fma2(acc[i][0], ad0, bp00);
                fma2(acc[i][1], ad0, bp01);
                fma2(acc[i][0], ad1, bp10);
                fma2(acc[i][1], ad1, bp11);
            }
        }
        __syncthreads();
        buf ^= 1;
    }
    #undef ISSUE_TILE

    #pragma unroll
    for (int i = 0; i < 8; i++) {
        int m = m0 + ty * 8 + i;
        float x0, x1, y0, y1;
        unpack2(acc[i][0], x0, x1);
        unpack2(acc[i][1], y0, y1);
        int nA = n0 + tx * 2, nB = nA + 32;
        if (bias && sp == 0) {
            x0 += bias[nA]; x1 += bias[nA + 1];
            y0 += bias[nB]; y1 += bias[nB + 1];
        }
        float* crow = Cm + (size_t)m * N;
        atomicAdd(crow + nA,     x0);
        atomicAdd(crow + nA + 1, x1);
        atomicAdd(crow + nB,     y0);
        atomicAdd(crow + nB + 1, y1);
    }
}

// ---------------------------------------------------------------------------
// attn split-K cp.async GEMM: 64x64 tiles, 256 THREADS (2x warps for latency
// hiding), grid (64, 2, 2); K=192 -> 2x96. atomicAdd into zeroed dATTN.
// ---------------------------------------------------------------------------
__global__ __launch_bounds__(256) void attn_ca(const float* __restrict__ We)
{
    __shared__ float As[2][64*36];
    __shared__ float Bs[2][32*64];

    const int bh = blockIdx.x, mh = blockIdx.y, sp = blockIdx.z;
    const int b  = bh >> 3, h = bh & 7;
    const int t  = threadIdx.x;
    const int tx = t & 15, ty = t >> 4;   // ty 0..15 -> 4 rows each
    const int kbase = sp * 96;

    const uint32_t asb = smem_u32(&As[0][0]);
    const uint32_t bsb = smem_u32(&Bs[0][0]);

    ull acc[4][2] = {};

    #define ISSUE_ATTN(buf, k0) do {                                            \
        _Pragma("unroll")                                                       \
        for (int r = 0; r < 2; r++) {                                           \
            int idx = t + r * 256;                                              \
            int m = idx >> 3, k4 = (idx & 7) << 2;                              \
            size_t row = (size_t)bh * LL + mh * 64 + m;                         \
            const float* src = ((k0) < 128)                                     \
                ? (dALPHA + row * LL + (k0) + k4)                               \
                : (dWsum  + row * EE + ((k0) - 128) + k4);                      \
            cp16(asb + (buf) * 9216u + (uint32_t)(m * 36 + k4) * 4u, src);      \
        }                                                                       \
        _Pragma("unroll")                                                       \
        for (int r = 0; r < 2; r++) {                                           \
            int idx = t + r * 256;                                              \
            int kk = idx >> 4, n4 = (idx & 15) << 2;                            \
            int kg = (k0) + kk;                                                 \
            const float* src = (kg < 128)                                       \
                ? (dKV_P + (size_t)(b * LL + kg) * DD + h * 64 + n4)            \
                : (We    + (size_t)(kg - 128) * DD + h * 64 + n4);              \
            cp16(bsb + (buf) * 8192u + (uint32_t)(kk * 64 + n4) * 4u, src);     \
        }                                                                       \
        cp_commit();                                                            \
    } while (0)

    ISSUE_ATTN(0, kbase);

    const int NT = 3;   // 96 per split
    int buf = 0;
    for (int kt = 0; kt < NT; kt++) {
        if (kt + 1 < NT) { ISSUE_ATTN(buf ^ 1, kbase + (kt + 1) * 32); cp_wait<1>(); }
        else             { cp_wait<0>(); }
        __syncthreads();

        #pragma unroll 4
        for (int kk = 0; kk < 32; kk += 2) {
            ull bp00 = *(const ull*)&Bs[buf][kk * 64 + tx * 2];
            ull bp01 = *(const ull*)&Bs[buf][kk * 64 + tx * 2 + 32];
            ull bp10 = *(const ull*)&Bs[buf][(kk + 1) * 64 + tx * 2];
            ull bp11 = *(const ull*)&Bs[buf][(kk + 1) * 64 + tx * 2 + 32];
            #pragma unroll
            for (int i = 0; i < 4; i++) {
                float2 af = *(const float2*)&As[buf][(ty * 4 + i) * 36 + kk];
                ull ad0 = pack2(af.x, af.x);
                ull ad1 = pack2(af.y, af.y);
                fma2(acc[i][0], ad0, bp00);
                fma2(acc[i][1], ad0, bp01);
                fma2(acc[i][0], ad1, bp10);
                fma2(acc[i][1], ad1, bp11);
            }
        }
        __syncthreads();
        buf ^= 1;
    }
    #undef ISSUE_ATTN

    #pragma unroll
    for (int i = 0; i < 4; i++) {
        int m = mh * 64 + ty * 4 + i;
        float* crow = dATTN_P + ((size_t)(b * LL) + m) * DD + h * 64;
        float x0, x1, y0, y1;
        unpack2(acc[i][0], x0, x1);
        unpack2(acc[i][1], y0, y1);
        atomicAdd(crow + tx * 2,      x0);
        atomicAdd(crow + tx * 2 + 1,  x1);
        atomicAdd(crow + tx * 2 + 32, y0);
        atomicAdd(crow + tx * 2 + 33, y1);
    }
}

// ---------------------------------------------------------------------------
// Merged s1 + g kernel (proven): 256 blocks x 256 threads.
// ---------------------------------------------------------------------------
__global__ __launch_bounds__(256) void s1g_kernel(const float* __restrict__ We)
{
    __shared__ float pool[8320];

    const int bx = blockIdx.x;
    const int t  = threadIdx.x;
    const int tx = t & 15, ty = t >> 4;

    if (bx < 128) {
        float* Qs = pool;            // [64][34]
        float* Ks = pool + 2176;     // [128][34]
        const int bh = bx >> 1, mh = bx & 1;
        const int b  = bh >> 3, h = bh & 7;

        ull acc[4][8] = {};

        for (int c0 = 0; c0 < 64; c0 += 32) {
            #pragma unroll
            for (int r = 0; r < 2; r++) {
                int idx = t + r * 256;
                int m   = idx >> 3;
                int c4  = (idx & 7) << 2;
                float4 v = *(const float4*)(dQ_P + (size_t)(b * LL + mh * 64 + m) * DD + h * 64 + c0 + c4);
                *(float2*)(Qs + m * 34 + c4)     = make_float2(v.x, v.y);
                *(float2*)(Qs + m * 34 + c4 + 2) = make_float2(v.z, v.w);
            }
            #pragma unroll
            for (int r = 0; r < 4; r++) {
                int idx = t + r * 256;
                int n   = idx >> 3;
                int c4  = (idx & 7) << 2;
                float4 v = *(const float4*)(dKV_P + (size_t)(b * LL + n) * DD + h * 64 + c0 + c4);
                *(float2*)(Ks + n * 34 + c4)     = make_float2(v.x, v.y);
                *(float2*)(Ks + n * 34 + c4 + 2) = make_float2(v.z, v.w);
            }
            __syncthreads();

            #pragma unroll
            for (int cc = 0; cc < 32; cc += 2) {
                ull a[4], b2[8];
                #pragma unroll
                for (int i = 0; i < 4; i++) a[i]  = *(const ull*)(Qs + (ty * 4 + i) * 34 + cc);
                #pragma unroll
                for (int j = 0; j < 8; j++) b2[j] = *(const ull*)(Ks + (tx + 16 * j) * 34 + cc);
                #pragma unroll
                for (int i = 0; i < 4; i++)
                    #pragma unroll
                    for (int j = 0; j < 8; j++)
                        fma2(acc[i][j], a[i], b2[j]);
            }
            __syncthreads();
        }

        #pragma unroll
        for (int i = 0; i < 4; i++) {
            int m = mh * 64 + ty * 4 + i;
            #pragma unroll
            for (int j = 0; j < 8; j++)
                dS1[((size_t)bh * LL + m) * LL + tx + 16 * j] = fsum2(acc[i][j]);
        }
    } else {
        float* Qs = pool;            // [64][65]
        float* Ws = pool + 4160;     // [64][65]
        const int idx0 = bx - 128;
        const int r0 = (idx0 >> 3) * 64;
        const int h  = idx0 & 7;

        #pragma unroll
        for (int r = 0; r < 4; r++) {
            int idx = t + r * 256;
            int m   = idx >> 4;
            int c4  = (idx & 15) << 2;
            float4 q = *(const float4*)(dQ_P + (size_t)(r0 + m) * DD + h * 64 + c4);
            Qs[m * 65 + c4 + 0] = q.x; Qs[m * 65 + c4 + 1] = q.y;
            Qs[m * 65 + c4 + 2] = q.z; Qs[m * 65 + c4 + 3] = q.w;
            float4 w = *(const float4*)(We + (size_t)m * DD + h * 64 + c4);
            Ws[m * 65 + c4 + 0] = w.x; Ws[m * 65 + c4 + 1] = w.y;
            Ws[m * 65 + c4 + 2] = w.z; Ws[m * 65 + c4 + 3] = w.w;
        }
        __syncthreads();

        float acc[4][4] = {};
        #pragma unroll
        for (int c = 0; c < 64; c++) {
            float a[4], b[4];
            #pragma unroll
            for (int i = 0; i < 4; i++) a[i] = Qs[(ty + 16 * i) * 65 + c];
            #pragma unroll
            for (int j = 0; j < 4; j++) b[j] = Ws[(tx + 16 * j) * 65 + c];
            #pragma unroll
            for (int i = 0; i < 4; i++)
                #pragma unroll
                for (int j = 0; j < 4; j++)
                    acc[i][j] += a[i] * b[j];
        }

        #pragma unroll
        for (int i = 0; i < 4; i++) {
            int m = r0 + ty + 16 * i;
            #pragma unroll
            for (int j = 0; j < 4; j++)
                dG[((size_t)m * HH + h) * EE + tx + 16 * j] = acc[i][j];
        }
    }
}

// ---------------------------------------------------------------------------
// Softmax v6 (proven): cp.async streaming; no max pass; fast divide.
// ---------------------------------------------------------------------------
__global__ __launch_bounds__(256, 5) void softmax6(
    const float* __restrict__ eptr, const int* __restrict__ adj)
{
    __shared__ float es[128 * 68];
    __shared__ float sS1[8 * 128];
    __shared__ float gT[512];
    __shared__ float aT[1024];
    __shared__ float redS[32];

    const int bq = blockIdx.x;
    const int b  = bq >> 7, q = bq & 127;
    const int t  = threadIdx.x;
    const int lane = t & 31, warp = t >> 5;

    const uint32_t esb  = smem_u32(es);
    const uint32_t s1b  = smem_u32(sS1);

    const float* erow = eptr + (size_t)bq * LL * EE;
    #pragma unroll
    for (int r = 0; r < 8; r++) {
        int idx = t + r * 256;
        int k   = idx >> 4;
        int j4  = (idx & 15) << 2;
        cp16(esb + (uint32_t)(k * 68 + j4) * 4u, erow + k * EE + j4);
    }
    {
        int h  = t >> 5;
        int k4 = (t & 31) << 2;
        cp16(s1b + (uint32_t)(h * 128 + k4) * 4u,
             dS1 + (((size_t)(b * HH + h)) * LL + q) * LL + k4);
    }
    cp_commit();

    #pragma unroll
    for (int i0 = 0; i0 < 2; i0++) {
        int i = t + i0 * 256;
        int h = i >> 6, j = i & 63;
        gT[j * 8 + h] = dG[(size_t)bq * 512 + i];
    }
    const int k  = t & 127;
    const int jh = t >> 7;
    int adjv = 1;
    if (t < 128) adjv = adj[(size_t)bq * LL + k];

    cp_wait<0>();
    __syncthreads();

    ull acc2[4] = {0, 0, 0, 0};
    #pragma unroll
    for (int j4 = 0; j4 < 8; j4++) {
        float4 ev4 = *(const float4*)(es + k * 68 + jh * 32 + j4 * 4);
        float evv[4] = {ev4.x, ev4.y, ev4.z, ev4.w};
        #pragma unroll
        for (int c = 0; c < 4; c++) {
            int j = jh * 32 + j4 * 4 + c;
            ull ed = pack2(evv[c], evv[c]);
            ulonglong2 g01 = *(const ulonglong2*)(gT + j * 8);
            ulonglong2 g23 = *(const ulonglong2*)(gT + j * 8 + 4);
            fma2(acc2[0], ed, g01.x); fma2(acc2[1], ed, g01.y);
            fma2(acc2[2], ed, g23.x); fma2(acc2[3], ed, g23.y);
        }
    }
    if (jh == 1) {
        *(ulonglong2*)(aT + k * 8)     = make_ulonglong2(acc2[0], acc2[1]);
        *(ulonglong2*)(aT + k * 8 + 4) = make_ulonglong2(acc2[2], acc2[3]);
    }
    __syncthreads();

    float p[8];
    if (t < 128) {
        float sv[8];
        ulonglong2 p01 = *(const ulonglong2*)(aT + k * 8);
        ulonglong2 p23 = *(const ulonglong2*)(aT + k * 8 + 4);
        add2(acc2[0], p01.x); add2(acc2[1], p01.y);
        add2(acc2[2], p23.x); add2(acc2[3], p23.y);
        unpack2(acc2[0], sv[0], sv[1]);
        unpack2(acc2[1], sv[2], sv[3]);
        unpack2(acc2[2], sv[4], sv[5]);
        unpack2(acc2[3], sv[6], sv[7]);
        #pragma unroll
        for (int h = 0; h < HH; h++) {
            float s = (sS1[h * 128 + k] + sv[h]) * 0.125f;
            s = (s > 0.f) ? s : 0.2f * s;
            p[h] = (adjv == 0) ? 0.f : __expf(s);
        }
        #pragma unroll
        for (int h = 0; h < HH; h++) {
            float s = p[h];
            #pragma unroll
            for (int o = 16; o > 0; o >>= 1) s += __shfl_xor_sync(0xffffffffu, s, o);
            if (lane == 0) redS[warp * 8 + h] = s;
        }
    }
    __syncthreads();

    if (t < 128) {
        float al[8];
        #pragma unroll
        for (int h = 0; h < HH; h++) {
            float tot = redS[h] + redS[8 + h] + redS[16 + h] + redS[24 + h];
            al[h] = __fdividef(p[h], tot);
            dALPHA[(((size_t)(b * HH + h)) * LL + q) * LL + k] = al[h];
        }
        *(float4*)(aT + k * 8)     = make_float4(al[0], al[1], al[2], al[3]);
        *(float4*)(aT + k * 8 + 4) = make_float4(al[4], al[5], al[6], al[7]);
    }
    __syncthreads();

    const int ei = t & 63, qt = t >> 6;
    ull w2[4] = {0, 0, 0, 0};
    #pragma unroll 8
    for (int kk = 0; kk < 32; kk++) {
        int kq = qt * 32 + kk;
        float ev = es[kq * 68 + ei];
        ull ed = pack2(ev, ev);
        ulonglong2 a01 = *(const ulonglong2*)(aT + kq * 8);
        ulonglong2 a23 = *(const ulonglong2*)(aT + kq * 8 + 4);
        fma2(w2[0], ed, a01.x); fma2(w2[1], ed, a01.y);
        fma2(w2[2], ed, a23.x); fma2(w2[3], ed, a23.y);
    }
    __syncthreads();

    if (qt == 1) {
        *(ulonglong2*)(aT + ei * 8)       = make_ulonglong2(w2[0], w2[1]);
        *(ulonglong2*)(aT + ei * 8 + 4)   = make_ulonglong2(w2[2], w2[3]);
    } else if (qt == 2) {
        *(ulonglong2*)(aT + 512 + ei * 8)     = make_ulonglong2(w2[0], w2[1]);
        *(ulonglong2*)(aT + 512 + ei * 8 + 4) = make_ulonglong2(w2[2], w2[3]);
    } else if (qt == 3) {
        *(ulonglong2*)(gT + ei * 8)       = make_ulonglong2(w2[0], w2[1]);
        *(ulonglong2*)(gT + ei * 8 + 4)   = make_ulonglong2(w2[2], w2[3]);
    }
    __syncthreads();

    if (qt == 0) {
        ulonglong2 s1a = *(const ulonglong2*)(aT + ei * 8);
        ulonglong2 s1b2 = *(const ulonglong2*)(aT + ei * 8 + 4);
        ulonglong2 s2a = *(const ulonglong2*)(aT + 512 + ei * 8);
        ulonglong2 s2b = *(const ulonglong2*)(aT + 512 + ei * 8 + 4);
        ulonglong2 s3a = *(const ulonglong2*)(gT + ei * 8);
        ulonglong2 s3b = *(const ulonglong2*)(gT + ei * 8 + 4);
        add2(w2[0], s1a.x); add2(w2[1], s1a.y); add2(w2[2], s1b2.x); add2(w2[3], s1b2.y);
        add2(w2[0], s2a.x); add2(w2[1], s2a.y); add2(w2[2], s2b.x);  add2(w2[3], s2b.y);
        add2(w2[0], s3a.x); add2(w2[1], s3a.y); add2(w2[2], s3b.x);  add2(w2[3], s3b.y);
        float w[8];
        unpack2(w2[0], w[0], w[1]); unpack2(w2[1], w[2], w[3]);
        unpack2(w2[2], w[4], w[5]); unpack2(w2[3], w[6], w[7]);
        #pragma unroll
        for (int h = 0; h < HH; h++)
            dWsum[(((size_t)(b * HH + h)) * LL + q) * EE + ei] = w[h];
    }
}

// ---------------------------------------------------------------------------
// LayerNorm + ReLU per row of 512
// ---------------------------------------------------------------------------
__global__ __launch_bounds__(256) void ln_kernel(
    const float* __restrict__ gamma, const float* __restrict__ beta,
    float* __restrict__ out)
{
    const int r = blockIdx.x;
    const int t = threadIdx.x;
    const int lane = t & 31, warp = t >> 5;

    float v0 = dFFN_P[(size_t)r * DD + t];
    float v1 = dFFN_P[(size_t)r * DD + 256 + t];
    float s  = v0 + v1;
    float sq = v0 * v0 + v1 * v1;

    __shared__ float rs[8], rq[8];
    __shared__ float mu_s, rstd_s;
    #pragma unroll
    for (int o = 16; o > 0; o >>= 1) {
        s  += __shfl_xor_sync(0xffffffffu, s, o);
        sq += __shfl_xor_sync(0xffffffffu, sq, o);
    }
    if (lane == 0) { rs[warp] = s; rq[warp] = sq; }
    __syncthreads();
    if (t == 0) {
        float S = 0.f, Q2 = 0.f;
        #pragma unroll
        for (int w = 0; w < 8; w++) { S += rs[w]; Q2 += rq[w]; }
        float mu  = S / 512.f;
        float var = Q2 / 512.f - mu * mu;
        mu_s = mu;
        rstd_s = rsqrtf(var + 1e-5f);
    }
    __syncthreads();
    float mu = mu_s, rstd = rstd_s;

    float y0 = (v0 - mu) * rstd * gamma[t]       + beta[t];
    float y1 = (v1 - mu) * rstd * gamma[256 + t] + beta[256 + t];
    out[(size_t)r * DD + t]       = fmaxf(y0, 0.f);
    out[(size_t)r * DD + 256 + t] = fmaxf(y1, 0.f);
}

// ---------------------------------------------------------------------------
extern "C" void kernel_launch(void* const* d_in, const int* in_sizes, int n_in,
                              void* d_out, int out_size)
{
    const float* x     = (const float*)d_in[0];
    const int*   adj   = (const int*)  d_in[1];
    const float* e     = (const float*)d_in[2];
    const float* Wq    = (const float*)d_in[3];
    const float* Wkv   = (const float*)d_in[4];
    const float* We    = (const float*)d_in[5];
    const float* Wf    = (const float*)d_in[6];
    const float* bf    = (const float*)d_in[7];
    const float* gamma = (const float*)d_in[8];
    const float* beta  = (const float*)d_in[9];
    float* out = (float*)d_out;

    float* pACC;
    cudaGetSymbolAddress((void**)&pACC, dACC);
    float* pQ    = pACC;
    float* pKV   = pACC + (size_t)BL * DD;
    float* pATTN = pACC + (size_t)2 * BL * DD;
    float* pFFN  = pACC + (size_t)3 * BL * DD;

    // 0. single memset for all split-K accumulation targets
    cudaMemsetAsync(pACC, 0, (size_t)4 * BL * DD * sizeof(float));

    // 1. Q = x@Wq, KV = x@Wkv  (split-K 2: 512 CTAs)
    gemm_ca<<<dim3(DD/64, BL/64, 4), 128>>>(x, Wq, pQ, Wkv, pKV, nullptr,
                                            DD, DD/2, DD, 2);
    // 2+3. S1 and g merged
    s1g_kernel<<<256, 256>>>(We);
    // 4. softmax
    softmax6<<<BL, 256>>>(e, adj);
    // 5. attention output (split-K 2, 256 threads/CTA)
    attn_ca<<<dim3(BB*HH, 2, 2), 256>>>(We);
    // 6. FFN GEMM with bias (split-K 2)
    gemm_ca<<<dim3(DD/64, BL/64, 2), 128>>>(pATTN, Wf, pFFN, nullptr, nullptr, bf,
                                            DD, DD/2, DD, 2);
    // 7. LayerNorm + ReLU
    ln_kernel<<<BL, 256>>>(gamma, beta, out);
}